// round 1
// baseline (speedup 1.0000x reference)
#include <cuda_runtime.h>

typedef unsigned long long u64;

#define DEPTH   64
#define DD      5
#define RPT     4     // rows per thread
#define G       2     // f32x2 groups per thread (2 rows each)
#define TPB     256
#define LSTRIDE 48    // u64 slots per layer in smem (5 rows x 8 + 5 bias + pad)

__device__ __forceinline__ u64 fma2(u64 a, u64 b, u64 c) {
    u64 d;
    asm("fma.rn.f32x2 %0, %1, %2, %3;" : "=l"(d) : "l"(a), "l"(b), "l"(c));
    return d;
}

__device__ __forceinline__ u64 pack2(float lo, float hi) {
    return (u64)__float_as_uint(lo) | ((u64)__float_as_uint(hi) << 32);
}

__device__ __forceinline__ u64 relu2(u64 v) {
    float lo = __uint_as_float((unsigned)v);
    float hi = __uint_as_float((unsigned)(v >> 32));
    lo = fmaxf(lo, 0.0f);
    hi = fmaxf(hi, 0.0f);
    return pack2(lo, hi);
}

__global__ __launch_bounds__(TPB)
void mlp5_kernel(const float* __restrict__ x,
                 const float* __restrict__ Ws,
                 const float* __restrict__ bs,
                 const float* __restrict__ Wo,
                 const float* __restrict__ bo,
                 float* __restrict__ out,
                 int batch)
{
    // Duplicated weights: each scalar stored as packed (w,w) u64 so a single
    // LDS.64/LDS.128 broadcast yields a ready f32x2 multiplier.
    // Layout per layer l (48 u64): [j*8 + i] = W[l][j][i] for i<5 (pad i=5..7),
    //                              [40 + j]  = b[l][j]     (pad 45..47)
    __shared__ u64 wd[DEPTH * LSTRIDE];

    for (int idx = threadIdx.x; idx < DEPTH * LSTRIDE; idx += TPB) {
        int l = idx / LSTRIDE, k = idx % LSTRIDE;
        float v = 0.0f;
        if (k < 40) {
            int j = k >> 3, i = k & 7;
            if (i < DD) v = Ws[l * 25 + j * DD + i];
        } else if (k < 45) {
            v = bs[l * DD + (k - 40)];
        }
        unsigned u = __float_as_uint(v);
        wd[idx] = (u64)u | ((u64)u << 32);
    }
    __syncthreads();

    int t = blockIdx.x * TPB + threadIdx.x;
    int row0 = t * RPT;
    if (row0 >= batch) return;

    // Load 4 rows x 5 feats = 20 floats = 5 x float4 (80B per thread, 16B aligned).
    float xs[RPT * DD];
    const float4* xp = (const float4*)(x + (size_t)row0 * DD);
    #pragma unroll
    for (int i = 0; i < RPT * DD / 4; i++)
        ((float4*)xs)[i] = xp[i];

    // Pack rows pairwise into f32x2 registers: h[g][i] = {row(2g)[i], row(2g+1)[i]}
    u64 h[G][DD];
    #pragma unroll
    for (int g = 0; g < G; g++)
        #pragma unroll
        for (int i = 0; i < DD; i++)
            h[g][i] = pack2(xs[(2 * g) * DD + i], xs[(2 * g + 1) * DD + i]);

    #pragma unroll 1
    for (int l = 0; l < DEPTH; l++) {
        const u64* wl = &wd[l * LSTRIDE];

        // Bias pairs (vectorized shared loads, 16B-aligned offsets)
        u64 bp[DD];
        {
            ulonglong2 b01 = *(const ulonglong2*)(wl + 40);
            ulonglong2 b23 = *(const ulonglong2*)(wl + 42);
            bp[0] = b01.x; bp[1] = b01.y; bp[2] = b23.x; bp[3] = b23.y;
            bp[4] = wl[44];
        }

        u64 acc[G][DD];
        #pragma unroll
        for (int j = 0; j < DD; j++) {
            ulonglong2 w01 = *(const ulonglong2*)(wl + j * 8 + 0);
            ulonglong2 w23 = *(const ulonglong2*)(wl + j * 8 + 2);
            u64 w4 = wl[j * 8 + 4];
            #pragma unroll
            for (int g = 0; g < G; g++) {
                u64 a = fma2(h[g][0], w01.x, bp[j]);
                a = fma2(h[g][1], w01.y, a);
                a = fma2(h[g][2], w23.x, a);
                a = fma2(h[g][3], w23.y, a);
                a = fma2(h[g][4], w4,   a);
                acc[g][j] = a;
            }
        }

        #pragma unroll
        for (int g = 0; g < G; g++)
            #pragma unroll
            for (int j = 0; j < DD; j++)
                h[g][j] = relu2(acc[g][j]);
    }

    // Final Linear(5,1)
    float wo[DD];
    #pragma unroll
    for (int i = 0; i < DD; i++) wo[i] = Wo[i];
    float bb = bo[0];

    float res[RPT];
    #pragma unroll
    for (int g = 0; g < G; g++) {
        float lo = bb, hi = bb;
        #pragma unroll
        for (int i = 0; i < DD; i++) {
            lo = fmaf(__uint_as_float((unsigned)(h[g][i])),       wo[i], lo);
            hi = fmaf(__uint_as_float((unsigned)(h[g][i] >> 32)), wo[i], hi);
        }
        res[2 * g]     = lo;
        res[2 * g + 1] = hi;
    }
    ((float4*)(out + row0))[0] = make_float4(res[0], res[1], res[2], res[3]);
}

extern "C" void kernel_launch(void* const* d_in, const int* in_sizes, int n_in,
                              void* d_out, int out_size)
{
    const float* x  = (const float*)d_in[0];
    const float* Ws = (const float*)d_in[1];
    const float* bs = (const float*)d_in[2];
    const float* Wo = (const float*)d_in[3];
    const float* bo = (const float*)d_in[4];
    float* out = (float*)d_out;

    int batch = in_sizes[0] / DD;            // 1048576
    int threads = (batch + RPT - 1) / RPT;   // 262144
    int blocks = (threads + TPB - 1) / TPB;  // 1024
    mlp5_kernel<<<blocks, TPB>>>(x, Ws, bs, Wo, bo, out, batch);
}